// round 14
// baseline (speedup 1.0000x reference)
#include <cuda_runtime.h>
#include <math.h>
#include <cstdint>

#define NN 20000
#define EE 320000
#define BB 64
#define HIDS 128
#define DEPTHS 4
#define NFREQS 8

// ---- scratch layout (floats) ----
#define OFF_H      0
#define OFF_HPRE   2560000
#define OFF_P      5120000
#define OFF_Q      7680000
#define OFF_F      10240000
#define OFF_CONV   30720000
#define OFF_S      33280000
#define OFF_T      33300000
#define OFF_BNSUM  33360000
#define OFF_BNSQ   33360128
#define OFF_U      33360256
#define OFF_V      33380256
#define OFF_LOGIT  33400256
#define OFF_EW     33420256
#define OFF_SCALE  33440256
#define OFF_SHIFT  33440384
#define OFF_POOLED 33440512
#define OFF_GMAX   33448704
#define OFF_GSUM   33448705
// ---- CSR int region (reinterpret as int) ----
#define IOFF_ROW   33448960   /* 20001 ints */
#define IOFF_CUR   33468964   /* 20000 ints */
#define IOFF_EID   33488964   /* 320000 ints */
#define IOFF_ESRC  33808964   /* 320000 ints */
#define OFF_ALPHA  34128976   /* 320000 floats: alpha (no longer aliases F) */

#define ZERO_LAYER_COUNT 80256    /* S + T + bnsum + bnsq */
#define ZERO_POOL_COUNT  8194

__device__ __align__(16) float g_scratch[34448976];

// ---------------- zero helper ----------------
__global__ void k_zero(int off, int count) {
    int i = blockIdx.x * 256 + threadIdx.x;
    if (i < count) g_scratch[off + i] = 0.0f;
}

// ================= CSR build (once per launch) =================
__global__ void k_hist(const int* __restrict__ ei) {
    int* __restrict__ deg = reinterpret_cast<int*>(g_scratch + IOFF_CUR);
    int e = blockIdx.x * 256 + threadIdx.x;
    if (e < EE) atomicAdd(&deg[ei[EE + e]], 1);
}

__global__ void k_scan() {
    const int* __restrict__ deg = reinterpret_cast<const int*>(g_scratch + IOFF_CUR);
    int* __restrict__ rowp = reinterpret_cast<int*>(g_scratch + IOFF_ROW);
    __shared__ int ssum[1024];
    int t = threadIdx.x;
    int base = t * 20;
    int run = 0;
    int pre[20];
#pragma unroll
    for (int i = 0; i < 20; i++) {
        int idx = base + i;
        int v = (idx < NN) ? deg[idx] : 0;
        pre[i] = run;
        run += v;
    }
    ssum[t] = run;
    __syncthreads();
    for (int off = 1; off < 1024; off <<= 1) {
        int v = (t >= off) ? ssum[t - off] : 0;
        __syncthreads();
        ssum[t] += v;
        __syncthreads();
    }
    int excl = ssum[t] - run;
#pragma unroll
    for (int i = 0; i < 20; i++) {
        int idx = base + i;
        if (idx < NN) rowp[idx] = excl + pre[i];
    }
    if (t == 0) rowp[NN] = EE;
}

__global__ void k_copycur() {
    const int* __restrict__ rowp = reinterpret_cast<const int*>(g_scratch + IOFF_ROW);
    int* __restrict__ cur = reinterpret_cast<int*>(g_scratch + IOFF_CUR);
    int i = blockIdx.x * 256 + threadIdx.x;
    if (i < NN) cur[i] = rowp[i];
}

__global__ void k_scatter(const int* __restrict__ ei) {
    int* __restrict__ cur = reinterpret_cast<int*>(g_scratch + IOFF_CUR);
    int* __restrict__ eid = reinterpret_cast<int*>(g_scratch + IOFF_EID);
    int* __restrict__ esrc = reinterpret_cast<int*>(g_scratch + IOFF_ESRC);
    int e = blockIdx.x * 256 + threadIdx.x;
    if (e >= EE) return;
    int dst = ei[EE + e];
    int pos = atomicAdd(&cur[dst], 1);
    eid[pos] = e;
    esrc[pos] = ei[e];
}

// ---------------- node encoder ----------------
__global__ void k_encode(const float* __restrict__ x,
                         const float* __restrict__ w,
                         const float* __restrict__ b) {
    float* __restrict__ h = g_scratch + OFF_H;
    int n = blockIdx.x;
    int c = threadIdx.x;
    float4 xv = *reinterpret_cast<const float4*>(x + n * 4);
    float acc = b[c];
    acc = fmaf(xv.x, w[0 * HIDS + c], acc);
    acc = fmaf(xv.y, w[1 * HIDS + c], acc);
    acc = fmaf(xv.z, w[2 * HIDS + c], acc);
    acc = fmaf(xv.w, w[3 * HIDS + c], acc);
    h[n * HIDS + c] = acc;
}

// ---------------- p/q GEMM: fkgemm-structured, grid=(313,2) ----------------
__global__ __launch_bounds__(128, 4) void k_pq(const float* __restrict__ W) {
    const float* __restrict__ h = g_scratch + OFF_H;
    float* __restrict__ out = g_scratch + (blockIdx.y ? OFF_Q : OFF_P);
    const float* __restrict__ Bm = W + (size_t)blockIdx.y * HIDS * HIDS;

    __shared__ __align__(16) float As[8][64];
    __shared__ __align__(16) float Bs[8][128];
    const int m0 = blockIdx.x * 64;
    const int tid = threadIdx.x;
    const int tcol = (tid & 15) * 8;
    const int trow = (tid >> 4) * 8;
    float acc[8][8];
#pragma unroll
    for (int i = 0; i < 8; i++)
#pragma unroll
        for (int j = 0; j < 8; j++) acc[i][j] = 0.f;

    const int arow = tid >> 1;
    const int acol = (tid & 1) * 4;
    const bool aval = (m0 + arow) < NN;
    const float* Aptr = h + (size_t)(m0 + arow) * HIDS + acol;

    for (int k0 = 0; k0 < HIDS; k0 += 8) {
        float4 av = make_float4(0.f, 0.f, 0.f, 0.f);
        if (aval) av = *reinterpret_cast<const float4*>(Aptr + k0);
        As[acol + 0][arow] = av.x;
        As[acol + 1][arow] = av.y;
        As[acol + 2][arow] = av.z;
        As[acol + 3][arow] = av.w;
#pragma unroll
        for (int i = 0; i < 2; i++) {
            int idx = tid + i * 128;
            int brow = idx >> 5;
            int bcol = (idx & 31) * 4;
            *reinterpret_cast<float4*>(&Bs[brow][bcol]) =
                *reinterpret_cast<const float4*>(Bm + (size_t)(k0 + brow) * HIDS + bcol);
        }
        __syncthreads();
#pragma unroll
        for (int k = 0; k < 8; k++) {
            float rm[8], rn[8];
            *reinterpret_cast<float4*>(rm)     = *reinterpret_cast<float4*>(&As[k][trow]);
            *reinterpret_cast<float4*>(rm + 4) = *reinterpret_cast<float4*>(&As[k][trow + 4]);
            *reinterpret_cast<float4*>(rn)     = *reinterpret_cast<float4*>(&Bs[k][tcol]);
            *reinterpret_cast<float4*>(rn + 4) = *reinterpret_cast<float4*>(&Bs[k][tcol + 4]);
#pragma unroll
            for (int i = 0; i < 8; i++)
#pragma unroll
                for (int j = 0; j < 8; j++) acc[i][j] = fmaf(rm[i], rn[j], acc[i][j]);
        }
        __syncthreads();
    }

#pragma unroll
    for (int r = 0; r < 8; r++) {
        int gm = m0 + trow + r;
        if (gm < NN) {
            *reinterpret_cast<float4*>(out + (size_t)gm * HIDS + tcol) =
                make_float4(acc[r][0], acc[r][1], acc[r][2], acc[r][3]);
            *reinterpret_cast<float4*>(out + (size_t)gm * HIDS + tcol + 4) =
                make_float4(acc[r][4], acc[r][5], acc[r][6], acc[r][7]);
        }
    }
}

// ---------------- u,v (warp per node; scalar aw loads) ----------------
__global__ void k_uv(const float* __restrict__ aw, const float* __restrict__ ab) {
    const float* __restrict__ h = g_scratch + OFF_H;
    float* __restrict__ u = g_scratch + OFF_U;
    float* __restrict__ v = g_scratch + OFF_V;
    int n = blockIdx.x * 8 + (threadIdx.x >> 5);
    if (n >= NN) return;
    int lane = threadIdx.x & 31;
    float4 hv = *reinterpret_cast<const float4*>(h + (size_t)n * HIDS + lane * 4);
    float a10 = aw[lane * 4 + 0], a11 = aw[lane * 4 + 1];
    float a12 = aw[lane * 4 + 2], a13 = aw[lane * 4 + 3];
    float a20 = aw[HIDS + lane * 4 + 0], a21 = aw[HIDS + lane * 4 + 1];
    float a22 = aw[HIDS + lane * 4 + 2], a23 = aw[HIDS + lane * 4 + 3];
    float su = hv.x * a10 + hv.y * a11 + hv.z * a12 + hv.w * a13;
    float sv = hv.x * a20 + hv.y * a21 + hv.z * a22 + hv.w * a23;
#pragma unroll
    for (int o = 16; o > 0; o >>= 1) {
        su += __shfl_xor_sync(0xffffffffu, su, o);
        sv += __shfl_xor_sync(0xffffffffu, sv, o);
    }
    if (lane == 0) { u[n] = su + ab[0]; v[n] = sv; }
}

// ---------------- alpha: thread per edge ----------------
__global__ void k_alpha(const int* __restrict__ ei, const float* __restrict__ ea,
                        const float* __restrict__ aw_tail) {
    const float* __restrict__ u = g_scratch + OFF_U;
    const float* __restrict__ v = g_scratch + OFF_V;
    float* __restrict__ alpha = g_scratch + OFF_ALPHA;
    float* __restrict__ S = g_scratch + OFF_S;
    float* __restrict__ T = g_scratch + OFF_T;
    int e = blockIdx.x * 256 + threadIdx.x;
    if (e >= EE) return;
    int src = ei[e];
    int dst = ei[EE + e];
    float e0 = ea[e * 3 + 0], e1 = ea[e * 3 + 1], e2 = ea[e * 3 + 2];
    float logit = u[dst] + v[src] + e0 * aw_tail[0] + e1 * aw_tail[1] + e2 * aw_tail[2];
    float a = 1.0f / (1.0f + expf(-logit));
    alpha[e] = a;
    atomicAdd(S + dst, a);
    atomicAdd(T + dst * 3 + 0, a * e0);
    atomicAdd(T + dst * 3 + 1, a * e1);
    atomicAdd(T + dst * 3 + 2, a * e2);
}

// ---------------- conv gather: warp per node over CSR ----------------
__global__ void k_conv() {
    const float* __restrict__ q = g_scratch + OFF_Q;
    const float* __restrict__ alpha = g_scratch + OFF_ALPHA;
    float* __restrict__ conv = g_scratch + OFF_CONV;
    const int* __restrict__ rowp = reinterpret_cast<const int*>(g_scratch + IOFF_ROW);
    const int* __restrict__ eid = reinterpret_cast<const int*>(g_scratch + IOFF_EID);
    const int* __restrict__ esrc = reinterpret_cast<const int*>(g_scratch + IOFF_ESRC);
    int n = blockIdx.x * 8 + (threadIdx.x >> 5);
    if (n >= NN) return;
    int lane = threadIdx.x & 31;
    int beg = rowp[n], end = rowp[n + 1];
    float4 acc = make_float4(0.f, 0.f, 0.f, 0.f);
    for (int base = beg; base < end; base += 32) {
        int i = base + lane;
        float a = 0.f;
        int s = 0;
        if (i < end) { a = alpha[eid[i]]; s = esrc[i]; }
        int cnt = min(32, end - base);
        for (int d = 0; d < cnt; d++) {
            float ad = __shfl_sync(0xffffffffu, a, d);
            int sd = __shfl_sync(0xffffffffu, s, d);
            float4 qv = *reinterpret_cast<const float4*>(q + (size_t)sd * HIDS + lane * 4);
            acc.x = fmaf(ad, qv.x, acc.x);
            acc.y = fmaf(ad, qv.y, acc.y);
            acc.z = fmaf(ad, qv.z, acc.z);
            acc.w = fmaf(ad, qv.w, acc.w);
        }
    }
    *reinterpret_cast<float4*>(conv + (size_t)n * HIDS + lane * 4) = acc;
}

// ---------------- FK features (standalone, used once after encode) -------------
__global__ void k_fkfeat() {
    const float* __restrict__ h = g_scratch + OFF_H;
    float* __restrict__ F = g_scratch + OFF_F;
    int n = blockIdx.x;
    int i = threadIdx.x;
    float hv = h[(size_t)n * HIDS + i];
    float s1, c1;
    sincospif(2.0f * hv, &s1, &c1);
    float s = s1, c = c1;
    float* Fr = F + (size_t)n * (NFREQS * HIDS) + i;
    Fr[0] = s + c;
#pragma unroll
    for (int k = 1; k < NFREQS; k++) {
        float ns = s * c1 + c * s1;
        float nc = c * c1 - s * s1;
        s = ns; c = nc;
        Fr[k * HIDS] = s + c;
    }
}

// ---------------- FK GEMM: BM=64, BN=128, BK=16, 8x8 micro, 128 thr ------------
__global__ __launch_bounds__(128, 4) void k_fkgemm(const float* __restrict__ Bm,
                                                   const float* __restrict__ linb,
                                                   const float* __restrict__ W3,
                                                   const float* __restrict__ fkb) {
    const float* __restrict__ A = g_scratch + OFF_F;
    const float* __restrict__ conv = g_scratch + OFF_CONV;
    const float* __restrict__ S = g_scratch + OFF_S;
    const float* __restrict__ T = g_scratch + OFF_T;
    const float* __restrict__ p = g_scratch + OFF_P;
    float* __restrict__ hpre = g_scratch + OFF_HPRE;
    float* __restrict__ bnsum = g_scratch + OFF_BNSUM;
    float* __restrict__ bnsq = g_scratch + OFF_BNSQ;

    __shared__ __align__(16) float As[16][64];
    __shared__ __align__(16) float Bs[16][128];
    __shared__ float sb1[128], sb2[128];
    const int m0 = blockIdx.x * 64;
    const int tid = threadIdx.x;
    const int tcol = (tid & 15) * 8;
    const int trow = (tid >> 4) * 8;
    float acc[8][8];
#pragma unroll
    for (int i = 0; i < 8; i++)
#pragma unroll
        for (int j = 0; j < 8; j++) acc[i][j] = 0.f;

    const int arow = tid >> 1;
    const int acol = (tid & 1) * 4;
    const bool aval = (m0 + arow) < NN;
    const float* Aptr = A + (size_t)(m0 + arow) * 1024 + acol;

    for (int k0 = 0; k0 < 1024; k0 += 16) {
        float4 av0 = make_float4(0.f, 0.f, 0.f, 0.f);
        float4 av1 = make_float4(0.f, 0.f, 0.f, 0.f);
        if (aval) {
            av0 = *reinterpret_cast<const float4*>(Aptr + k0);
            av1 = *reinterpret_cast<const float4*>(Aptr + k0 + 8);
        }
        As[acol + 0][arow] = av0.x;
        As[acol + 1][arow] = av0.y;
        As[acol + 2][arow] = av0.z;
        As[acol + 3][arow] = av0.w;
        As[acol + 8][arow] = av1.x;
        As[acol + 9][arow] = av1.y;
        As[acol + 10][arow] = av1.z;
        As[acol + 11][arow] = av1.w;
#pragma unroll
        for (int i = 0; i < 4; i++) {
            int idx = tid + i * 128;
            int brow = idx >> 5;
            int bcol = (idx & 31) * 4;
            *reinterpret_cast<float4*>(&Bs[brow][bcol]) =
                *reinterpret_cast<const float4*>(Bm + (size_t)(k0 + brow) * 128 + bcol);
        }
        __syncthreads();
#pragma unroll
        for (int k = 0; k < 16; k++) {
            float rm[8], rn[8];
            *reinterpret_cast<float4*>(rm)     = *reinterpret_cast<float4*>(&As[k][trow]);
            *reinterpret_cast<float4*>(rm + 4) = *reinterpret_cast<float4*>(&As[k][trow + 4]);
            *reinterpret_cast<float4*>(rn)     = *reinterpret_cast<float4*>(&Bs[k][tcol]);
            *reinterpret_cast<float4*>(rn + 4) = *reinterpret_cast<float4*>(&Bs[k][tcol + 4]);
#pragma unroll
            for (int i = 0; i < 8; i++)
#pragma unroll
                for (int j = 0; j < 8; j++) acc[i][j] = fmaf(rm[i], rn[j], acc[i][j]);
        }
        __syncthreads();
    }

    // fused epilogue: hpre = fk + conv + S*(p+lin_b) + T@W3 + fk_b, + BN stats
    float colsum[8], colsq[8];
#pragma unroll
    for (int j = 0; j < 8; j++) { colsum[j] = 0.f; colsq[j] = 0.f; }
#pragma unroll
    for (int r = 0; r < 8; r++) {
        int m = m0 + trow + r;
        if (m < NN) {
            float Sv = S[m];
            float t0 = T[m * 3], t1 = T[m * 3 + 1], t2 = T[m * 3 + 2];
#pragma unroll
            for (int j = 0; j < 8; j++) {
                int c = tcol + j;
                float val = acc[r][j] + conv[(size_t)m * HIDS + c]
                          + Sv * (p[(size_t)m * HIDS + c] + linb[c])
                          + t0 * W3[c] + t1 * W3[HIDS + c] + t2 * W3[2 * HIDS + c]
                          + fkb[c];
                hpre[(size_t)m * HIDS + c] = val;
                colsum[j] += val;
                colsq[j] += val * val;
            }
        }
    }
    sb1[tid] = 0.f; sb2[tid] = 0.f;
    __syncthreads();
#pragma unroll
    for (int j = 0; j < 8; j++) {
        atomicAdd(&sb1[tcol + j], colsum[j]);
        atomicAdd(&sb2[tcol + j], colsq[j]);
    }
    __syncthreads();
    atomicAdd(&bnsum[tid], sb1[tid]);
    atomicAdd(&bnsq[tid], sb2[tid]);
}

// ---------------- BN finalize ----------------
__global__ void k_bnfin(const float* __restrict__ g, const float* __restrict__ b) {
    const float* bnsum = g_scratch + OFF_BNSUM;
    const float* bnsq = g_scratch + OFF_BNSQ;
    float* scale = g_scratch + OFF_SCALE;
    float* shift = g_scratch + OFF_SHIFT;
    int c = threadIdx.x;
    float mu = bnsum[c] * (1.0f / NN);
    float var = bnsq[c] * (1.0f / NN) - mu * mu;
    var = fmaxf(var, 0.0f);
    float sc = g[c] / sqrtf(var + 1e-5f);
    scale[c] = sc;
    shift[c] = b[c] - mu * sc;
}

// ---------------- fused BN apply + ReLU + FK features ----------------
__global__ void k_applyfk(int compute_f) {
    const float* __restrict__ hpre = g_scratch + OFF_HPRE;
    const float* __restrict__ scale = g_scratch + OFF_SCALE;
    const float* __restrict__ shift = g_scratch + OFF_SHIFT;
    float* __restrict__ h = g_scratch + OFF_H;
    float* __restrict__ F = g_scratch + OFF_F;
    int n = blockIdx.x;
    int i = threadIdx.x;
    size_t idx = (size_t)n * HIDS + i;
    float hv = fmaxf(fmaf(hpre[idx], scale[i], shift[i]), 0.0f);
    h[idx] = hv;
    if (compute_f) {
        float s1, c1;
        sincospif(2.0f * hv, &s1, &c1);
        float s = s1, c = c1;
        float* Fr = F + (size_t)n * (NFREQS * HIDS) + i;
        Fr[0] = s + c;
#pragma unroll
        for (int k = 1; k < NFREQS; k++) {
            float ns = s * c1 + c * s1;
            float nc = c * c1 - s * s1;
            s = ns; c = nc;
            Fr[k * HIDS] = s + c;
        }
    }
}

// ---------------- pool logits + global max (warp per node) ----------------
__global__ void k_logit(const float* __restrict__ pw, const float* __restrict__ pb) {
    const float* h = g_scratch + OFF_H;
    float* logit = g_scratch + OFF_LOGIT;
    unsigned* gmax = reinterpret_cast<unsigned*>(g_scratch + OFF_GMAX);
    int n = blockIdx.x * 8 + (threadIdx.x >> 5);
    if (n >= NN) return;
    int lane = threadIdx.x & 31;
    float4 hv = *reinterpret_cast<const float4*>(h + (size_t)n * HIDS + lane * 4);
    float4 wv = *reinterpret_cast<const float4*>(pw + lane * 4);
    float s = hv.x * wv.x + hv.y * wv.y + hv.z * wv.z + hv.w * wv.w;
#pragma unroll
    for (int o = 16; o > 0; o >>= 1) s += __shfl_xor_sync(0xffffffffu, s, o);
    if (lane == 0) {
        float lg = s + pb[0];
        logit[n] = lg;
        unsigned enc = __float_as_uint(lg);
        enc = (enc & 0x80000000u) ? ~enc : (enc | 0x80000000u);
        atomicMax(gmax, enc);
    }
}

// ---------------- exp + global sum ----------------
__global__ void k_exp() {
    const float* logit = g_scratch + OFF_LOGIT;
    const unsigned* gmax = reinterpret_cast<const unsigned*>(g_scratch + OFF_GMAX);
    float* ew = g_scratch + OFF_EW;
    float* gsum = g_scratch + OFF_GSUM;
    __shared__ float red[256];
    int n = blockIdx.x * 256 + threadIdx.x;
    float lsum = 0.f;
    if (n < NN) {
        unsigned enc = *gmax;
        float mx = (enc & 0x80000000u) ? __uint_as_float(enc ^ 0x80000000u)
                                       : __uint_as_float(~enc);
        float ev = expf(logit[n] - mx);
        ew[n] = ev;
        lsum = ev;
    }
    red[threadIdx.x] = lsum;
    __syncthreads();
    for (int s = 128; s > 0; s >>= 1) {
        if (threadIdx.x < s) red[threadIdx.x] += red[threadIdx.x + s];
        __syncthreads();
    }
    if (threadIdx.x == 0) atomicAdd(gsum, red[0]);
}

// ---------------- weighted segment pool (warp per node) ----------------
__global__ void k_pool(const int* __restrict__ batch) {
    const float* h = g_scratch + OFF_H;
    const float* ew = g_scratch + OFF_EW;
    const float* gsum = g_scratch + OFF_GSUM;
    float* pooled = g_scratch + OFF_POOLED;
    int n = blockIdx.x * 8 + (threadIdx.x >> 5);
    if (n >= NN) return;
    int lane = threadIdx.x & 31;
    float coef = ew[n] / gsum[0];
    int b = batch[n];
    float4 hv = *reinterpret_cast<const float4*>(h + (size_t)n * HIDS + lane * 4);
    atomicAdd(reinterpret_cast<float4*>(pooled + (size_t)b * HIDS + lane * 4),
              make_float4(coef * hv.x, coef * hv.y, coef * hv.z, coef * hv.w));
}

// ---------------- heads (block per batch element) ----------------
__global__ void k_heads(const float* __restrict__ sgt, const int* __restrict__ sg,
                        const float* __restrict__ w1, const float* __restrict__ b1,
                        const float* __restrict__ ew2, const float* __restrict__ eb2,
                        const float* __restrict__ sw2, const float* __restrict__ sb2,
                        const float* __restrict__ cw2, const float* __restrict__ cb2,
                        const float* __restrict__ mw2, const float* __restrict__ mb2,
                        float* __restrict__ out) {
    const float* pooled = g_scratch + OFF_POOLED;
    int b = blockIdx.x;
    int c = threadIdx.x;
    __shared__ float comb[256];
    __shared__ float z[128];
    comb[c] = pooled[(size_t)b * HIDS + c];
    comb[128 + c] = sgt[(size_t)sg[b] * HIDS + c];
    __syncthreads();
    const float* w2s[4] = { ew2, sw2, cw2, mw2 };
    const float* b2s[4] = { eb2, sb2, cb2, mb2 };
    const int odArr[4] = { 1, 3, 7, 3 };
    const int ooff[4] = { 0, 64, 256, 704 };
    for (int i = 0; i < 4; i++) {
        float a = b1[i * HIDS + c];
        const float* W = w1 + (size_t)i * 256 * HIDS;
        for (int k = 0; k < 256; k++) a = fmaf(comb[k], W[(size_t)k * HIDS + c], a);
        z[c] = fmaxf(a, 0.0f);
        __syncthreads();
        int od = odArr[i];
        if (c < od) {
            float s = b2s[i][c];
            const float* w2 = w2s[i];
            for (int k = 0; k < HIDS; k++) s = fmaf(z[k], w2[k * od + c], s);
            out[ooff[i] + b * od + c] = s;
        }
        __syncthreads();
    }
}

// ---------------- launcher ----------------
extern "C" void kernel_launch(void* const* d_in, const int* in_sizes, int n_in,
                              void* d_out, int out_size) {
    const float* x        = (const float*)d_in[0];
    const int*   ei       = (const int*)d_in[1];
    const float* ea       = (const float*)d_in[2];
    const int*   batch    = (const int*)d_in[3];
    const int*   sg       = (const int*)d_in[4];
    const float* node_w   = (const float*)d_in[5];
    const float* node_b   = (const float*)d_in[6];
    const float* sg_table = (const float*)d_in[7];
    const float* lin_w    = (const float*)d_in[8];
    const float* lin_b    = (const float*)d_in[9];
    const float* att_w    = (const float*)d_in[10];
    const float* att_b    = (const float*)d_in[11];
    const float* fk_w     = (const float*)d_in[12];
    const float* fk_b     = (const float*)d_in[13];
    const float* bn_g     = (const float*)d_in[14];
    const float* bn_b     = (const float*)d_in[15];
    const float* pool_w   = (const float*)d_in[16];
    const float* pool_b   = (const float*)d_in[17];
    const float* head_w1  = (const float*)d_in[18];
    const float* head_b1  = (const float*)d_in[19];
    const float* e_w2 = (const float*)d_in[20]; const float* e_b2 = (const float*)d_in[21];
    const float* s_w2 = (const float*)d_in[22]; const float* s_b2 = (const float*)d_in[23];
    const float* c_w2 = (const float*)d_in[24]; const float* c_b2 = (const float*)d_in[25];
    const float* m_w2 = (const float*)d_in[26]; const float* m_b2 = (const float*)d_in[27];
    float* out = (float*)d_out;

    // ---- one-time CSR build ----
    k_zero<<<(NN + 255) / 256, 256>>>(IOFF_CUR, NN);
    k_hist<<<(EE + 255) / 256, 256>>>(ei);
    k_scan<<<1, 1024>>>();
    k_copycur<<<(NN + 255) / 256, 256>>>();
    k_scatter<<<(EE + 255) / 256, 256>>>(ei);

    k_encode<<<NN, 128>>>(x, node_w, node_b);
    k_fkfeat<<<NN, 128>>>();   // F for layer 0

    dim3 pq_grid((NN + 63) / 64, 2);
    for (int l = 0; l < DEPTHS; l++) {
        k_zero<<<(ZERO_LAYER_COUNT + 255) / 256, 256>>>(OFF_S, ZERO_LAYER_COUNT);
        k_pq<<<pq_grid, 128>>>(lin_w + (size_t)l * 259 * HIDS);
        k_uv<<<(NN + 7) / 8, 256>>>(att_w + (size_t)l * 259, att_b + l);
        k_alpha<<<(EE + 255) / 256, 256>>>(ei, ea, att_w + (size_t)l * 259 + 256);
        k_conv<<<(NN + 7) / 8, 256>>>();
        k_fkgemm<<<(NN + 63) / 64, 128>>>(fk_w + (size_t)l * NFREQS * HIDS * HIDS,
                                          lin_b + (size_t)l * HIDS,
                                          lin_w + (size_t)l * 259 * HIDS + 256 * HIDS,
                                          fk_b + (size_t)l * HIDS);
        k_bnfin<<<1, 128>>>(bn_g + (size_t)l * HIDS, bn_b + (size_t)l * HIDS);
        k_applyfk<<<NN, 128>>>(l < DEPTHS - 1 ? 1 : 0);
    }

    k_zero<<<(ZERO_POOL_COUNT + 255) / 256, 256>>>(OFF_POOLED, ZERO_POOL_COUNT);
    k_logit<<<(NN + 7) / 8, 256>>>(pool_w, pool_b);
    k_exp<<<(NN + 255) / 256, 256>>>();
    k_pool<<<(NN + 7) / 8, 256>>>(batch);
    k_heads<<<BB, 128>>>(sg_table, sg, head_w1, head_b1,
                         e_w2, e_b2, s_w2, s_b2, c_w2, c_b2, m_w2, m_b2, out);
}

// round 17
// speedup vs baseline: 1.4369x; 1.4369x over previous
#include <cuda_runtime.h>
#include <math.h>
#include <cstdint>

#define NN 20000
#define EE 320000
#define BB 64
#define HIDS 128
#define DEPTHS 4
#define NFREQS 8

// ---- scratch layout (floats) ----
#define OFF_H      0
#define OFF_HPRE   2560000
#define OFF_P      5120000
#define OFF_Q      7680000
#define OFF_F      10240000
#define OFF_CONV   30720000
#define OFF_S      33280000
#define OFF_T      33300000
#define OFF_BNSUM  33360000
#define OFF_BNSQ   33360128
#define OFF_U      33360256
#define OFF_V      33380256
#define OFF_LOGIT  33400256
#define OFF_EW     33420256
#define OFF_SCALE  33440256
#define OFF_SHIFT  33440384
#define OFF_POOLED 33440512
#define OFF_GMAX   33448704
#define OFF_GSUM   33448705
// ---- CSR int region (reinterpret as int) ----
#define IOFF_ROW   33448960   /* 20001 ints */
#define IOFF_CUR   33468964   /* 20000 ints */
#define IOFF_EID   33488964   /* 320000 ints */
#define IOFF_ESRC  33808964   /* 320000 ints */
#define OFF_ALPHA  34128976   /* 320000 floats: alpha (dedicated, no aliasing) */

#define ZERO_LAYER_COUNT 80256    /* S + T + bnsum + bnsq */
#define ZERO_POOL_COUNT  8194

__device__ __align__(16) float g_scratch[34448976];

// ---------------- zero helper ----------------
__global__ void k_zero(int off, int count) {
    int i = blockIdx.x * 256 + threadIdx.x;
    if (i < count) g_scratch[off + i] = 0.0f;
}

// ================= CSR build (once per launch) =================
__global__ void k_hist(const int* __restrict__ ei) {
    int* __restrict__ deg = reinterpret_cast<int*>(g_scratch + IOFF_CUR);
    int e = blockIdx.x * 256 + threadIdx.x;
    if (e < EE) atomicAdd(&deg[ei[EE + e]], 1);
}

__global__ void k_scan() {
    const int* __restrict__ deg = reinterpret_cast<const int*>(g_scratch + IOFF_CUR);
    int* __restrict__ rowp = reinterpret_cast<int*>(g_scratch + IOFF_ROW);
    __shared__ int ssum[1024];
    int t = threadIdx.x;
    int base = t * 20;
    int run = 0;
    int pre[20];
#pragma unroll
    for (int i = 0; i < 20; i++) {
        int idx = base + i;
        int v = (idx < NN) ? deg[idx] : 0;
        pre[i] = run;
        run += v;
    }
    ssum[t] = run;
    __syncthreads();
    for (int off = 1; off < 1024; off <<= 1) {
        int v = (t >= off) ? ssum[t - off] : 0;
        __syncthreads();
        ssum[t] += v;
        __syncthreads();
    }
    int excl = ssum[t] - run;
#pragma unroll
    for (int i = 0; i < 20; i++) {
        int idx = base + i;
        if (idx < NN) rowp[idx] = excl + pre[i];
    }
    if (t == 0) rowp[NN] = EE;
}

__global__ void k_copycur() {
    const int* __restrict__ rowp = reinterpret_cast<const int*>(g_scratch + IOFF_ROW);
    int* __restrict__ cur = reinterpret_cast<int*>(g_scratch + IOFF_CUR);
    int i = blockIdx.x * 256 + threadIdx.x;
    if (i < NN) cur[i] = rowp[i];
}

__global__ void k_scatter(const int* __restrict__ ei) {
    int* __restrict__ cur = reinterpret_cast<int*>(g_scratch + IOFF_CUR);
    int* __restrict__ eid = reinterpret_cast<int*>(g_scratch + IOFF_EID);
    int* __restrict__ esrc = reinterpret_cast<int*>(g_scratch + IOFF_ESRC);
    int e = blockIdx.x * 256 + threadIdx.x;
    if (e >= EE) return;
    int dst = ei[EE + e];
    int pos = atomicAdd(&cur[dst], 1);
    eid[pos] = e;
    esrc[pos] = ei[e];
}

// ---------------- node encoder ----------------
__global__ void k_encode(const float* __restrict__ x,
                         const float* __restrict__ w,
                         const float* __restrict__ b) {
    float* __restrict__ h = g_scratch + OFF_H;
    int n = blockIdx.x;
    int c = threadIdx.x;
    float4 xv = *reinterpret_cast<const float4*>(x + n * 4);
    float acc = b[c];
    acc = fmaf(xv.x, w[0 * HIDS + c], acc);
    acc = fmaf(xv.y, w[1 * HIDS + c], acc);
    acc = fmaf(xv.z, w[2 * HIDS + c], acc);
    acc = fmaf(xv.w, w[3 * HIDS + c], acc);
    h[n * HIDS + c] = acc;
}

// ---------------- p/q GEMM: fkgemm-structured, grid=(313,2) ----------------
__global__ __launch_bounds__(128, 4) void k_pq(const float* __restrict__ W) {
    const float* __restrict__ h = g_scratch + OFF_H;
    float* __restrict__ out = g_scratch + (blockIdx.y ? OFF_Q : OFF_P);
    const float* __restrict__ Bm = W + (size_t)blockIdx.y * HIDS * HIDS;

    __shared__ __align__(16) float As[8][64];
    __shared__ __align__(16) float Bs[8][128];
    const int m0 = blockIdx.x * 64;
    const int tid = threadIdx.x;
    const int tcol = (tid & 15) * 8;
    const int trow = (tid >> 4) * 8;
    float acc[8][8];
#pragma unroll
    for (int i = 0; i < 8; i++)
#pragma unroll
        for (int j = 0; j < 8; j++) acc[i][j] = 0.f;

    const int arow = tid >> 1;
    const int acol = (tid & 1) * 4;
    const bool aval = (m0 + arow) < NN;
    const float* Aptr = h + (size_t)(m0 + arow) * HIDS + acol;

    for (int k0 = 0; k0 < HIDS; k0 += 8) {
        float4 av = make_float4(0.f, 0.f, 0.f, 0.f);
        if (aval) av = *reinterpret_cast<const float4*>(Aptr + k0);
        As[acol + 0][arow] = av.x;
        As[acol + 1][arow] = av.y;
        As[acol + 2][arow] = av.z;
        As[acol + 3][arow] = av.w;
#pragma unroll
        for (int i = 0; i < 2; i++) {
            int idx = tid + i * 128;
            int brow = idx >> 5;
            int bcol = (idx & 31) * 4;
            *reinterpret_cast<float4*>(&Bs[brow][bcol]) =
                *reinterpret_cast<const float4*>(Bm + (size_t)(k0 + brow) * HIDS + bcol);
        }
        __syncthreads();
#pragma unroll
        for (int k = 0; k < 8; k++) {
            float rm[8], rn[8];
            *reinterpret_cast<float4*>(rm)     = *reinterpret_cast<float4*>(&As[k][trow]);
            *reinterpret_cast<float4*>(rm + 4) = *reinterpret_cast<float4*>(&As[k][trow + 4]);
            *reinterpret_cast<float4*>(rn)     = *reinterpret_cast<float4*>(&Bs[k][tcol]);
            *reinterpret_cast<float4*>(rn + 4) = *reinterpret_cast<float4*>(&Bs[k][tcol + 4]);
#pragma unroll
            for (int i = 0; i < 8; i++)
#pragma unroll
                for (int j = 0; j < 8; j++) acc[i][j] = fmaf(rm[i], rn[j], acc[i][j]);
        }
        __syncthreads();
    }

#pragma unroll
    for (int r = 0; r < 8; r++) {
        int gm = m0 + trow + r;
        if (gm < NN) {
            *reinterpret_cast<float4*>(out + (size_t)gm * HIDS + tcol) =
                make_float4(acc[r][0], acc[r][1], acc[r][2], acc[r][3]);
            *reinterpret_cast<float4*>(out + (size_t)gm * HIDS + tcol + 4) =
                make_float4(acc[r][4], acc[r][5], acc[r][6], acc[r][7]);
        }
    }
}

// ---------------- u,v (warp per node; scalar aw loads) ----------------
__global__ void k_uv(const float* __restrict__ aw, const float* __restrict__ ab) {
    const float* __restrict__ h = g_scratch + OFF_H;
    float* __restrict__ u = g_scratch + OFF_U;
    float* __restrict__ v = g_scratch + OFF_V;
    int n = blockIdx.x * 8 + (threadIdx.x >> 5);
    if (n >= NN) return;
    int lane = threadIdx.x & 31;
    float4 hv = *reinterpret_cast<const float4*>(h + (size_t)n * HIDS + lane * 4);
    float a10 = aw[lane * 4 + 0], a11 = aw[lane * 4 + 1];
    float a12 = aw[lane * 4 + 2], a13 = aw[lane * 4 + 3];
    float a20 = aw[HIDS + lane * 4 + 0], a21 = aw[HIDS + lane * 4 + 1];
    float a22 = aw[HIDS + lane * 4 + 2], a23 = aw[HIDS + lane * 4 + 3];
    float su = hv.x * a10 + hv.y * a11 + hv.z * a12 + hv.w * a13;
    float sv = hv.x * a20 + hv.y * a21 + hv.z * a22 + hv.w * a23;
#pragma unroll
    for (int o = 16; o > 0; o >>= 1) {
        su += __shfl_xor_sync(0xffffffffu, su, o);
        sv += __shfl_xor_sync(0xffffffffu, sv, o);
    }
    if (lane == 0) { u[n] = su + ab[0]; v[n] = sv; }
}

// ---------------- alpha: thread per edge ----------------
__global__ void k_alpha(const int* __restrict__ ei, const float* __restrict__ ea,
                        const float* __restrict__ aw_tail) {
    const float* __restrict__ u = g_scratch + OFF_U;
    const float* __restrict__ v = g_scratch + OFF_V;
    float* __restrict__ alpha = g_scratch + OFF_ALPHA;
    float* __restrict__ S = g_scratch + OFF_S;
    float* __restrict__ T = g_scratch + OFF_T;
    int e = blockIdx.x * 256 + threadIdx.x;
    if (e >= EE) return;
    int src = ei[e];
    int dst = ei[EE + e];
    float e0 = ea[e * 3 + 0], e1 = ea[e * 3 + 1], e2 = ea[e * 3 + 2];
    float logit = u[dst] + v[src] + e0 * aw_tail[0] + e1 * aw_tail[1] + e2 * aw_tail[2];
    float a = 1.0f / (1.0f + expf(-logit));
    alpha[e] = a;
    atomicAdd(S + dst, a);
    atomicAdd(T + dst * 3 + 0, a * e0);
    atomicAdd(T + dst * 3 + 1, a * e1);
    atomicAdd(T + dst * 3 + 2, a * e2);
}

// ---------------- conv gather: warp per node over CSR ----------------
__global__ void k_conv() {
    const float* __restrict__ q = g_scratch + OFF_Q;
    const float* __restrict__ alpha = g_scratch + OFF_ALPHA;
    float* __restrict__ conv = g_scratch + OFF_CONV;
    const int* __restrict__ rowp = reinterpret_cast<const int*>(g_scratch + IOFF_ROW);
    const int* __restrict__ eid = reinterpret_cast<const int*>(g_scratch + IOFF_EID);
    const int* __restrict__ esrc = reinterpret_cast<const int*>(g_scratch + IOFF_ESRC);
    int n = blockIdx.x * 8 + (threadIdx.x >> 5);
    if (n >= NN) return;
    int lane = threadIdx.x & 31;
    int beg = rowp[n], end = rowp[n + 1];
    float4 acc = make_float4(0.f, 0.f, 0.f, 0.f);
    for (int base = beg; base < end; base += 32) {
        int i = base + lane;
        float a = 0.f;
        int s = 0;
        if (i < end) { a = alpha[eid[i]]; s = esrc[i]; }
        int cnt = min(32, end - base);
        for (int d = 0; d < cnt; d++) {
            float ad = __shfl_sync(0xffffffffu, a, d);
            int sd = __shfl_sync(0xffffffffu, s, d);
            float4 qv = *reinterpret_cast<const float4*>(q + (size_t)sd * HIDS + lane * 4);
            acc.x = fmaf(ad, qv.x, acc.x);
            acc.y = fmaf(ad, qv.y, acc.y);
            acc.z = fmaf(ad, qv.z, acc.z);
            acc.w = fmaf(ad, qv.w, acc.w);
        }
    }
    *reinterpret_cast<float4*>(conv + (size_t)n * HIDS + lane * 4) = acc;
}

// ---------------- FK features (standalone; used once after encode) -------------
__global__ void k_fkfeat() {
    const float* __restrict__ h = g_scratch + OFF_H;
    float* __restrict__ F = g_scratch + OFF_F;
    int n = blockIdx.x;
    int i = threadIdx.x;
    float hv = h[(size_t)n * HIDS + i];
    float s1, c1;
    sincospif(2.0f * hv, &s1, &c1);
    float s = s1, c = c1;
    float* Fr = F + (size_t)n * (NFREQS * HIDS) + i;
    Fr[0] = s + c;
#pragma unroll
    for (int k = 1; k < NFREQS; k++) {
        float ns = s * c1 + c * s1;
        float nc = c * c1 - s * s1;
        s = ns; c = nc;
        Fr[k * HIDS] = s + c;
    }
}

// ---------------- FK GEMM: BM=64, BN=128, BK=8, 8x8 micro, 128 thr (proven) ----
__global__ __launch_bounds__(128, 4) void k_fkgemm(const float* __restrict__ Bm,
                                                   const float* __restrict__ linb,
                                                   const float* __restrict__ W3,
                                                   const float* __restrict__ fkb) {
    const float* __restrict__ A = g_scratch + OFF_F;
    const float* __restrict__ conv = g_scratch + OFF_CONV;
    const float* __restrict__ S = g_scratch + OFF_S;
    const float* __restrict__ T = g_scratch + OFF_T;
    const float* __restrict__ p = g_scratch + OFF_P;
    float* __restrict__ hpre = g_scratch + OFF_HPRE;
    float* __restrict__ bnsum = g_scratch + OFF_BNSUM;
    float* __restrict__ bnsq = g_scratch + OFF_BNSQ;

    __shared__ __align__(16) float As[8][64];
    __shared__ __align__(16) float Bs[8][128];
    __shared__ float sb1[128], sb2[128];
    const int m0 = blockIdx.x * 64;
    const int tid = threadIdx.x;
    const int tcol = (tid & 15) * 8;
    const int trow = (tid >> 4) * 8;
    float acc[8][8];
#pragma unroll
    for (int i = 0; i < 8; i++)
#pragma unroll
        for (int j = 0; j < 8; j++) acc[i][j] = 0.f;

    const int arow = tid >> 1;
    const int acol = (tid & 1) * 4;
    const bool aval = (m0 + arow) < NN;
    const float* Aptr = A + (size_t)(m0 + arow) * 1024 + acol;

    for (int k0 = 0; k0 < 1024; k0 += 8) {
        float4 av = make_float4(0.f, 0.f, 0.f, 0.f);
        if (aval) av = *reinterpret_cast<const float4*>(Aptr + k0);
        As[acol + 0][arow] = av.x;
        As[acol + 1][arow] = av.y;
        As[acol + 2][arow] = av.z;
        As[acol + 3][arow] = av.w;
#pragma unroll
        for (int i = 0; i < 2; i++) {
            int idx = tid + i * 128;
            int brow = idx >> 5;
            int bcol = (idx & 31) * 4;
            *reinterpret_cast<float4*>(&Bs[brow][bcol]) =
                *reinterpret_cast<const float4*>(Bm + (size_t)(k0 + brow) * 128 + bcol);
        }
        __syncthreads();
#pragma unroll
        for (int k = 0; k < 8; k++) {
            float rm[8], rn[8];
            *reinterpret_cast<float4*>(rm)     = *reinterpret_cast<float4*>(&As[k][trow]);
            *reinterpret_cast<float4*>(rm + 4) = *reinterpret_cast<float4*>(&As[k][trow + 4]);
            *reinterpret_cast<float4*>(rn)     = *reinterpret_cast<float4*>(&Bs[k][tcol]);
            *reinterpret_cast<float4*>(rn + 4) = *reinterpret_cast<float4*>(&Bs[k][tcol + 4]);
#pragma unroll
            for (int i = 0; i < 8; i++)
#pragma unroll
                for (int j = 0; j < 8; j++) acc[i][j] = fmaf(rm[i], rn[j], acc[i][j]);
        }
        __syncthreads();
    }

    // fused epilogue: hpre = fk + conv + S*(p+lin_b) + T@W3 + fk_b, + BN stats
    float colsum[8], colsq[8];
#pragma unroll
    for (int j = 0; j < 8; j++) { colsum[j] = 0.f; colsq[j] = 0.f; }
#pragma unroll
    for (int r = 0; r < 8; r++) {
        int m = m0 + trow + r;
        if (m < NN) {
            float Sv = S[m];
            float t0 = T[m * 3], t1 = T[m * 3 + 1], t2 = T[m * 3 + 2];
#pragma unroll
            for (int j = 0; j < 8; j++) {
                int c = tcol + j;
                float val = acc[r][j] + conv[(size_t)m * HIDS + c]
                          + Sv * (p[(size_t)m * HIDS + c] + linb[c])
                          + t0 * W3[c] + t1 * W3[HIDS + c] + t2 * W3[2 * HIDS + c]
                          + fkb[c];
                hpre[(size_t)m * HIDS + c] = val;
                colsum[j] += val;
                colsq[j] += val * val;
            }
        }
    }
    sb1[tid] = 0.f; sb2[tid] = 0.f;
    __syncthreads();
#pragma unroll
    for (int j = 0; j < 8; j++) {
        atomicAdd(&sb1[tcol + j], colsum[j]);
        atomicAdd(&sb2[tcol + j], colsq[j]);
    }
    __syncthreads();
    atomicAdd(&bnsum[tid], sb1[tid]);
    atomicAdd(&bnsq[tid], sb2[tid]);
}

// ---------------- BN finalize ----------------
__global__ void k_bnfin(const float* __restrict__ g, const float* __restrict__ b) {
    const float* bnsum = g_scratch + OFF_BNSUM;
    const float* bnsq = g_scratch + OFF_BNSQ;
    float* scale = g_scratch + OFF_SCALE;
    float* shift = g_scratch + OFF_SHIFT;
    int c = threadIdx.x;
    float mu = bnsum[c] * (1.0f / NN);
    float var = bnsq[c] * (1.0f / NN) - mu * mu;
    var = fmaxf(var, 0.0f);
    float sc = g[c] / sqrtf(var + 1e-5f);
    scale[c] = sc;
    shift[c] = b[c] - mu * sc;
}

// ---------------- fused BN apply + ReLU + FK features ----------------
__global__ void k_applyfk(int compute_f) {
    const float* __restrict__ hpre = g_scratch + OFF_HPRE;
    const float* __restrict__ scale = g_scratch + OFF_SCALE;
    const float* __restrict__ shift = g_scratch + OFF_SHIFT;
    float* __restrict__ h = g_scratch + OFF_H;
    float* __restrict__ F = g_scratch + OFF_F;
    int n = blockIdx.x;
    int i = threadIdx.x;
    size_t idx = (size_t)n * HIDS + i;
    float hv = fmaxf(fmaf(hpre[idx], scale[i], shift[i]), 0.0f);
    h[idx] = hv;
    if (compute_f) {
        float s1, c1;
        sincospif(2.0f * hv, &s1, &c1);
        float s = s1, c = c1;
        float* Fr = F + (size_t)n * (NFREQS * HIDS) + i;
        Fr[0] = s + c;
#pragma unroll
        for (int k = 1; k < NFREQS; k++) {
            float ns = s * c1 + c * s1;
            float nc = c * c1 - s * s1;
            s = ns; c = nc;
            Fr[k * HIDS] = s + c;
        }
    }
}

// ---------------- pool logits + global max (warp per node) ----------------
__global__ void k_logit(const float* __restrict__ pw, const float* __restrict__ pb) {
    const float* h = g_scratch + OFF_H;
    float* logit = g_scratch + OFF_LOGIT;
    unsigned* gmax = reinterpret_cast<unsigned*>(g_scratch + OFF_GMAX);
    int n = blockIdx.x * 8 + (threadIdx.x >> 5);
    if (n >= NN) return;
    int lane = threadIdx.x & 31;
    float4 hv = *reinterpret_cast<const float4*>(h + (size_t)n * HIDS + lane * 4);
    float4 wv = *reinterpret_cast<const float4*>(pw + lane * 4);
    float s = hv.x * wv.x + hv.y * wv.y + hv.z * wv.z + hv.w * wv.w;
#pragma unroll
    for (int o = 16; o > 0; o >>= 1) s += __shfl_xor_sync(0xffffffffu, s, o);
    if (lane == 0) {
        float lg = s + pb[0];
        logit[n] = lg;
        unsigned enc = __float_as_uint(lg);
        enc = (enc & 0x80000000u) ? ~enc : (enc | 0x80000000u);
        atomicMax(gmax, enc);
    }
}

// ---------------- exp + global sum ----------------
__global__ void k_exp() {
    const float* logit = g_scratch + OFF_LOGIT;
    const unsigned* gmax = reinterpret_cast<const unsigned*>(g_scratch + OFF_GMAX);
    float* ew = g_scratch + OFF_EW;
    float* gsum = g_scratch + OFF_GSUM;
    __shared__ float red[256];
    int n = blockIdx.x * 256 + threadIdx.x;
    float lsum = 0.f;
    if (n < NN) {
        unsigned enc = *gmax;
        float mx = (enc & 0x80000000u) ? __uint_as_float(enc ^ 0x80000000u)
                                       : __uint_as_float(~enc);
        float ev = expf(logit[n] - mx);
        ew[n] = ev;
        lsum = ev;
    }
    red[threadIdx.x] = lsum;
    __syncthreads();
    for (int s = 128; s > 0; s >>= 1) {
        if (threadIdx.x < s) red[threadIdx.x] += red[threadIdx.x + s];
        __syncthreads();
    }
    if (threadIdx.x == 0) atomicAdd(gsum, red[0]);
}

// ---------------- weighted segment pool (warp per node) ----------------
__global__ void k_pool(const int* __restrict__ batch) {
    const float* h = g_scratch + OFF_H;
    const float* ew = g_scratch + OFF_EW;
    const float* gsum = g_scratch + OFF_GSUM;
    float* pooled = g_scratch + OFF_POOLED;
    int n = blockIdx.x * 8 + (threadIdx.x >> 5);
    if (n >= NN) return;
    int lane = threadIdx.x & 31;
    float coef = ew[n] / gsum[0];
    int b = batch[n];
    float4 hv = *reinterpret_cast<const float4*>(h + (size_t)n * HIDS + lane * 4);
    atomicAdd(reinterpret_cast<float4*>(pooled + (size_t)b * HIDS + lane * 4),
              make_float4(coef * hv.x, coef * hv.y, coef * hv.z, coef * hv.w));
}

// ---------------- heads (block per batch element) ----------------
__global__ void k_heads(const float* __restrict__ sgt, const int* __restrict__ sg,
                        const float* __restrict__ w1, const float* __restrict__ b1,
                        const float* __restrict__ ew2, const float* __restrict__ eb2,
                        const float* __restrict__ sw2, const float* __restrict__ sb2,
                        const float* __restrict__ cw2, const float* __restrict__ cb2,
                        const float* __restrict__ mw2, const float* __restrict__ mb2,
                        float* __restrict__ out) {
    const float* pooled = g_scratch + OFF_POOLED;
    int b = blockIdx.x;
    int c = threadIdx.x;
    __shared__ float comb[256];
    __shared__ float z[128];
    comb[c] = pooled[(size_t)b * HIDS + c];
    comb[128 + c] = sgt[(size_t)sg[b] * HIDS + c];
    __syncthreads();
    const float* w2s[4] = { ew2, sw2, cw2, mw2 };
    const float* b2s[4] = { eb2, sb2, cb2, mb2 };
    const int odArr[4] = { 1, 3, 7, 3 };
    const int ooff[4] = { 0, 64, 256, 704 };
    for (int i = 0; i < 4; i++) {
        float a = b1[i * HIDS + c];
        const float* W = w1 + (size_t)i * 256 * HIDS;
        for (int k = 0; k < 256; k++) a = fmaf(comb[k], W[(size_t)k * HIDS + c], a);
        z[c] = fmaxf(a, 0.0f);
        __syncthreads();
        int od = odArr[i];
        if (c < od) {
            float s = b2s[i][c];
            const float* w2 = w2s[i];
            for (int k = 0; k < HIDS; k++) s = fmaf(z[k], w2[k * od + c], s);
            out[ooff[i] + b * od + c] = s;
        }
        __syncthreads();
    }
}

// ---------------- launcher ----------------
extern "C" void kernel_launch(void* const* d_in, const int* in_sizes, int n_in,
                              void* d_out, int out_size) {
    const float* x        = (const float*)d_in[0];
    const int*   ei       = (const int*)d_in[1];
    const float* ea       = (const float*)d_in[2];
    const int*   batch    = (const int*)d_in[3];
    const int*   sg       = (const int*)d_in[4];
    const float* node_w   = (const float*)d_in[5];
    const float* node_b   = (const float*)d_in[6];
    const float* sg_table = (const float*)d_in[7];
    const float* lin_w    = (const float*)d_in[8];
    const float* lin_b    = (const float*)d_in[9];
    const float* att_w    = (const float*)d_in[10];
    const float* att_b    = (const float*)d_in[11];
    const float* fk_w     = (const float*)d_in[12];
    const float* fk_b     = (const float*)d_in[13];
    const float* bn_g     = (const float*)d_in[14];
    const float* bn_b     = (const float*)d_in[15];
    const float* pool_w   = (const float*)d_in[16];
    const float* pool_b   = (const float*)d_in[17];
    const float* head_w1  = (const float*)d_in[18];
    const float* head_b1  = (const float*)d_in[19];
    const float* e_w2 = (const float*)d_in[20]; const float* e_b2 = (const float*)d_in[21];
    const float* s_w2 = (const float*)d_in[22]; const float* s_b2 = (const float*)d_in[23];
    const float* c_w2 = (const float*)d_in[24]; const float* c_b2 = (const float*)d_in[25];
    const float* m_w2 = (const float*)d_in[26]; const float* m_b2 = (const float*)d_in[27];
    float* out = (float*)d_out;

    // ---- one-time CSR build ----
    k_zero<<<(NN + 255) / 256, 256>>>(IOFF_CUR, NN);
    k_hist<<<(EE + 255) / 256, 256>>>(ei);
    k_scan<<<1, 1024>>>();
    k_copycur<<<(NN + 255) / 256, 256>>>();
    k_scatter<<<(EE + 255) / 256, 256>>>(ei);

    k_encode<<<NN, 128>>>(x, node_w, node_b);
    k_fkfeat<<<NN, 128>>>();   // F for layer 0

    dim3 pq_grid((NN + 63) / 64, 2);
    for (int l = 0; l < DEPTHS; l++) {
        k_zero<<<(ZERO_LAYER_COUNT + 255) / 256, 256>>>(OFF_S, ZERO_LAYER_COUNT);
        k_pq<<<pq_grid, 128>>>(lin_w + (size_t)l * 259 * HIDS);
        k_uv<<<(NN + 7) / 8, 256>>>(att_w + (size_t)l * 259, att_b + l);
        k_alpha<<<(EE + 255) / 256, 256>>>(ei, ea, att_w + (size_t)l * 259 + 256);
        k_conv<<<(NN + 7) / 8, 256>>>();
        k_fkgemm<<<(NN + 63) / 64, 128>>>(fk_w + (size_t)l * NFREQS * HIDS * HIDS,
                                          lin_b + (size_t)l * HIDS,
                                          lin_w + (size_t)l * 259 * HIDS + 256 * HIDS,
                                          fk_b + (size_t)l * HIDS);
        k_bnfin<<<1, 128>>>(bn_g + (size_t)l * HIDS, bn_b + (size_t)l * HIDS);
        k_applyfk<<<NN, 128>>>(l < DEPTHS - 1 ? 1 : 0);
    }

    k_zero<<<(ZERO_POOL_COUNT + 255) / 256, 256>>>(OFF_POOLED, ZERO_POOL_COUNT);
    k_logit<<<(NN + 7) / 8, 256>>>(pool_w, pool_b);
    k_exp<<<(NN + 255) / 256, 256>>>();
    k_pool<<<(NN + 7) / 8, 256>>>(batch);
    k_heads<<<BB, 128>>>(sg_table, sg, head_w1, head_b1,
                         e_w2, e_b2, s_w2, s_b2, c_w2, c_b2, m_w2, m_b2, out);
}